// round 7
// baseline (speedup 1.0000x reference)
#include <cuda_runtime.h>
#include <cuda_bf16.h>
#include <cstdint>

// RBF kernel matrix, filter + concurrent zero-fill + sparse scatter.
//   sq_hi from hi-bf16 HMMA GEMM.
//   Bound: |sq_hi - sq| <= 0.008*(||x||^2+||y||^2)  (bf16 rn eps=2^-8, AM-GM, margin)
//   sq_hi >= 89.2 + 0.008*(x2+y2)  =>  sq > 88  =>  expf(-sq) underflows => 0.0f
//   else: exact fp32 recompute, appended to a sparse list, scattered at the end.
// Output zeros are written by a dedicated streaming kernel running CONCURRENTLY
// (forked capture stream) with the MMA filter kernel.
// x,y: [8192,128] f32. out: [8192,8192] f32.

#define NM 8192
#define KD 128
#define CTA_M 128
#define CTA_N 128
#define LIST_CAP (1u << 22)   // 4M entries

__device__ float g_x2[NM];
__device__ float g_y2[NM];
__device__ __nv_bfloat16 g_xhi[NM * KD];
__device__ __nv_bfloat16 g_yhi[NM * KD];
__device__ unsigned int g_cnt;
__device__ uint2 g_list[LIST_CAP];

// ---------------- helpers ----------------
__device__ __forceinline__ uint32_t smem_u32(const void* p) {
    uint32_t a;
    asm("{ .reg .u64 t; cvta.to.shared.u64 t, %1; cvt.u32.u64 %0, t; }"
        : "=r"(a) : "l"(p));
    return a;
}
__device__ __forceinline__ void ldsm_x4(uint32_t* r, uint32_t addr) {
    asm volatile("ldmatrix.sync.aligned.m8n8.x4.shared.b16 {%0,%1,%2,%3}, [%4];"
                 : "=r"(r[0]), "=r"(r[1]), "=r"(r[2]), "=r"(r[3]) : "r"(addr));
}
__device__ __forceinline__ void mma_bf16(float* d, const uint32_t* a, const uint32_t* b) {
    asm volatile(
        "mma.sync.aligned.m16n8k16.row.col.f32.bf16.bf16.f32 "
        "{%0,%1,%2,%3}, {%4,%5,%6,%7}, {%8,%9}, {%0,%1,%2,%3};"
        : "+f"(d[0]), "+f"(d[1]), "+f"(d[2]), "+f"(d[3])
        : "r"(a[0]), "r"(a[1]), "r"(a[2]), "r"(a[3]), "r"(b[0]), "r"(b[1]));
}
__device__ __forceinline__ void cp16(uint32_t dst, const void* src) {
    asm volatile("cp.async.cg.shared.global [%0], [%1], 16;" :: "r"(dst), "l"(src));
}
__device__ __forceinline__ uint32_t bits(__nv_bfloat162 v) {
    return *reinterpret_cast<uint32_t*>(&v);
}

// exact value for non-underflow elements (rare): fp32 dot from global
__device__ __noinline__ float precise_val(const float* __restrict__ X,
                                          const float* __restrict__ Y,
                                          int m, int n, float xpy) {
    const float4* xr = reinterpret_cast<const float4*>(X + (size_t)m * KD);
    const float4* yr = reinterpret_cast<const float4*>(Y + (size_t)n * KD);
    float dot = 0.0f;
#pragma unroll
    for (int i = 0; i < KD / 4; i++) {
        float4 a = xr[i], b = yr[i];
        dot = fmaf(a.x, b.x, dot); dot = fmaf(a.y, b.y, dot);
        dot = fmaf(a.z, b.z, dot); dot = fmaf(a.w, b.w, dot);
    }
    return __expf(-fmaxf(fmaf(-2.0f, dot, xpy), 0.0f));
}

__device__ __forceinline__ void emit(const float* X, const float* Y,
                                     int m, int n, float sq_hi, float xpy) {
    if (sq_hi < 89.2f + 0.008f * xpy) {
        float v = precise_val(X, Y, m, n, xpy);
        unsigned pos = atomicAdd(&g_cnt, 1u);
        if (pos < LIST_CAP)
            g_list[pos] = make_uint2((unsigned)(m * NM + n), __float_as_uint(v));
    }
}

// ---------------- zero-fill (streaming, concurrent stream) ----------------
__global__ void rbf_zerofill_kernel(float4* __restrict__ o) {
    const int n4 = NM * NM / 4;
    int i = blockIdx.x * blockDim.x + threadIdx.x;
    int stride = gridDim.x * blockDim.x;
    const float4 z = make_float4(0.f, 0.f, 0.f, 0.f);
    for (; i < n4; i += stride) o[i] = z;
}

// ---------------- prep: norms + bf16 hi (warp per row) + counter reset ----------------
__global__ void rbf_prep_kernel(const float* __restrict__ x,
                                const float* __restrict__ y) {
    if (blockIdx.x == 0 && threadIdx.x == 0) g_cnt = 0u;
    int gw = (blockIdx.x * blockDim.x + threadIdx.x) >> 5;
    int lane = threadIdx.x & 31;
    if (gw >= 2 * NM) return;
    bool isX = gw < NM;
    int row = isX ? gw : gw - NM;
    const float* src = isX ? x : y;
    __nv_bfloat16* hid = isX ? g_xhi : g_yhi;
    float* nrm = isX ? g_x2 : g_y2;

    float4 v = reinterpret_cast<const float4*>(src + (size_t)row * KD)[lane];
    __nv_bfloat162 h01 = __floats2bfloat162_rn(v.x, v.y);
    __nv_bfloat162 h23 = __floats2bfloat162_rn(v.z, v.w);
    *reinterpret_cast<uint2*>(hid + (size_t)row * KD + lane * 4) =
        make_uint2(bits(h01), bits(h23));

    float s = fmaf(v.x, v.x, fmaf(v.y, v.y, fmaf(v.z, v.z, v.w * v.w)));
#pragma unroll
    for (int o = 16; o > 0; o >>= 1) s += __shfl_xor_sync(0xFFFFFFFFu, s, o);
    if (lane == 0) nrm[row] = s;
}

// ---------------- main MMA filter kernel (NO dense output stores) ----------------
// CTA 128x128, 8 warps (2 M x 4 N), warp tile 64x32, full K=128 resident.
// smem 64 KB (2 CTA/SM): Ahi [0,32K) = 2 k-panels x 16 KB (128 rows x 128B,
// 8 x 16B chunks, chunk ^= row&7); Bhi [32K,64K) same.
__global__ __launch_bounds__(256, 2)
void rbf_mma_kernel(const float* __restrict__ X,
                    const float* __restrict__ Y) {
    extern __shared__ char sm[];
    __shared__ float x2s[CTA_M];
    __shared__ float y2s[CTA_N];

    const int tid = threadIdx.x;
    const int wid = tid >> 5;
    const int lane = tid & 31;
    const int wm = wid >> 2;       // 0..1 (64 rows)
    const int wn = wid & 3;        // 0..3 (32 cols)
    const int mBase = blockIdx.y * CTA_M;
    const int nBase = blockIdx.x * CTA_N;

    const uint32_t sA = smem_u32(sm);
    const uint32_t sB = sA + 32768u;

#pragma unroll
    for (int i = 0; i < 8; i++) {
        int idx = tid + i * 256;
        int r = idx >> 4, j = idx & 15;
        uint32_t off = (uint32_t)((j >> 3) * 16384 + r * 128 + (((j & 7) ^ (r & 7)) << 4));
        cp16(sA + off, g_xhi + (size_t)(mBase + r) * KD + j * 8);
        cp16(sB + off, g_yhi + (size_t)(nBase + r) * KD + j * 8);
    }
    asm volatile("cp.async.commit_group;" ::: "memory");

    if (tid < CTA_M) x2s[tid] = g_x2[mBase + tid];
    else             y2s[tid - CTA_M] = g_y2[nBase + (tid - CTA_M)];

    float acc[4][4][4];
#pragma unroll
    for (int mt = 0; mt < 4; mt++)
#pragma unroll
        for (int nt = 0; nt < 4; nt++)
#pragma unroll
            for (int r = 0; r < 4; r++) acc[mt][nt][r] = 0.0f;

    const int a_row = wm * 64 + (lane & 15);
    const int a_cs  = lane >> 4;
    const int b_row = wn * 32 + (lane & 7) + ((lane >> 4) << 3);
    const int b_cs  = (lane >> 3) & 1;

    asm volatile("cp.async.wait_group 0;" ::: "memory");
    __syncthreads();

#pragma unroll
    for (int ks = 0; ks < 8; ks++) {
        const uint32_t pnl = (uint32_t)((ks >> 2) * 16384);
        const int kc = (ks & 3) * 2;
        uint32_t bh[2][4];
#pragma unroll
        for (int pr = 0; pr < 2; pr++) {
            int rr = b_row + pr * 16;
            ldsm_x4(bh[pr], sB + pnl + (uint32_t)(rr * 128)
                          + (uint32_t)(((kc + b_cs) ^ (rr & 7)) << 4));
        }
#pragma unroll
        for (int mt = 0; mt < 4; mt++) {
            int rr = a_row + mt * 16;
            uint32_t ah[4];
            ldsm_x4(ah, sA + pnl + (uint32_t)(rr * 128)
                      + (uint32_t)(((kc + a_cs) ^ (rr & 7)) << 4));
#pragma unroll
            for (int pr = 0; pr < 2; pr++) {
                mma_bf16(acc[mt][2 * pr],     ah, bh[pr]);
                mma_bf16(acc[mt][2 * pr + 1], ah, bh[pr] + 2);
            }
        }
    }

    // -------- epilogue: certify underflow; rare elements go to the list --------
    const int g  = lane >> 2;
    const int t4 = lane & 3;
#pragma unroll
    for (int mt = 0; mt < 4; mt++) {
        int mrow = wm * 64 + mt * 16 + g;
        float xa = x2s[mrow];
        float xb = x2s[mrow + 8];
        int m0 = mBase + mrow;
#pragma unroll
        for (int nt = 0; nt < 4; nt++) {
            int nc = wn * 32 + nt * 8 + t4 * 2;
            float ya = y2s[nc];
            float yb = y2s[nc + 1];
            const float* a4 = acc[mt][nt];
            int n0 = nBase + nc;
            emit(X, Y, m0,     n0,     fmaf(-2.0f, a4[0], xa + ya), xa + ya);
            emit(X, Y, m0,     n0 + 1, fmaf(-2.0f, a4[1], xa + yb), xa + yb);
            emit(X, Y, m0 + 8, n0,     fmaf(-2.0f, a4[2], xb + ya), xb + ya);
            emit(X, Y, m0 + 8, n0 + 1, fmaf(-2.0f, a4[3], xb + yb), xb + yb);
        }
    }
}

// ---------------- scatter (after zerofill + mma join) ----------------
__global__ void rbf_scatter_kernel(float* __restrict__ O,
                                   const float* __restrict__ X,
                                   const float* __restrict__ Y) {
    unsigned cnt = g_cnt;
    int i = blockIdx.x * blockDim.x + threadIdx.x;
    int stride = gridDim.x * blockDim.x;
    if (cnt <= LIST_CAP) {
        for (unsigned k = i; k < cnt; k += stride) {
            uint2 e = g_list[k];
            O[e.x] = __uint_as_float(e.y);
        }
    } else {
        // overflow fallback: full precise recompute (never hit on sane data)
        for (long long idx = i; idx < (long long)NM * NM; idx += stride) {
            int m = (int)(idx >> 13), n = (int)(idx & (NM - 1));
            float xpy = g_x2[m] + g_y2[n];
            O[idx] = precise_val(X, Y, m, n, xpy);
        }
    }
}

// ---------------------------------------------------------------------------
extern "C" void kernel_launch(void* const* d_in, const int* in_sizes, int n_in,
                              void* d_out, int out_size) {
    const float* x = (const float*)d_in[0];
    const float* y = (const float*)d_in[1];
    float* out = (float*)d_out;

    static cudaStream_t s2 = nullptr;
    static cudaEvent_t evFork = nullptr, evJoin = nullptr;
    if (!s2) {
        cudaStreamCreateWithFlags(&s2, cudaStreamNonBlocking);
        cudaEventCreateWithFlags(&evFork, cudaEventDisableTiming);
        cudaEventCreateWithFlags(&evJoin, cudaEventDisableTiming);
        cudaFuncSetAttribute(rbf_mma_kernel,
                             cudaFuncAttributeMaxDynamicSharedMemorySize, 65536);
    }

    // fork: zerofill runs concurrently with prep+mma
    cudaEventRecord(evFork, 0);
    cudaStreamWaitEvent(s2, evFork, 0);
    rbf_zerofill_kernel<<<4096, 256, 0, s2>>>((float4*)out);
    cudaEventRecord(evJoin, s2);

    rbf_prep_kernel<<<2048, 256>>>(x, y);
    dim3 grid(NM / CTA_N, NM / CTA_M);   // (64, 64)
    rbf_mma_kernel<<<grid, 256, 65536>>>(x, y);

    // join: scatter after both zerofill and mma
    cudaStreamWaitEvent(0, evJoin, 0);
    rbf_scatter_kernel<<<2048, 256>>>(out, x, y);
}

// round 8
// speedup vs baseline: 1.2764x; 1.2764x over previous
#include <cuda_runtime.h>
#include <cuda_bf16.h>
#include <cstdint>

// RBF kernel matrix, filter + fused coalesced zero-store + rare precise overwrite.
//   sq_hi from hi-bf16 HMMA GEMM.
//   Bound: |sq_hi - sq| <= 0.008*(||x||^2+||y||^2)  (bf16 rn eps=2^-8, AM-GM, margin)
//   sq_hi >= 89.2 + 0.008*(x2+y2)  =>  sq > 88  =>  expf(-sq) underflows => 0.0f
//   else: exact fp32 recompute written directly (rare).
// x,y: [8192,128] f32. out: [8192,8192] f32.

#define NM 8192
#define KD 128
#define CTA_M 128
#define CTA_N 128

__device__ float g_x2[NM];
__device__ float g_y2[NM];
__device__ __nv_bfloat16 g_xhi[NM * KD];
__device__ __nv_bfloat16 g_yhi[NM * KD];

// ---------------- helpers ----------------
__device__ __forceinline__ uint32_t smem_u32(const void* p) {
    uint32_t a;
    asm("{ .reg .u64 t; cvta.to.shared.u64 t, %1; cvt.u32.u64 %0, t; }"
        : "=r"(a) : "l"(p));
    return a;
}
__device__ __forceinline__ void ldsm_x4(uint32_t* r, uint32_t addr) {
    asm volatile("ldmatrix.sync.aligned.m8n8.x4.shared.b16 {%0,%1,%2,%3}, [%4];"
                 : "=r"(r[0]), "=r"(r[1]), "=r"(r[2]), "=r"(r[3]) : "r"(addr));
}
__device__ __forceinline__ void mma_bf16(float* d, const uint32_t* a, const uint32_t* b) {
    asm volatile(
        "mma.sync.aligned.m16n8k16.row.col.f32.bf16.bf16.f32 "
        "{%0,%1,%2,%3}, {%4,%5,%6,%7}, {%8,%9}, {%0,%1,%2,%3};"
        : "+f"(d[0]), "+f"(d[1]), "+f"(d[2]), "+f"(d[3])
        : "r"(a[0]), "r"(a[1]), "r"(a[2]), "r"(a[3]), "r"(b[0]), "r"(b[1]));
}
__device__ __forceinline__ void cp16(uint32_t dst, const void* src) {
    asm volatile("cp.async.cg.shared.global [%0], [%1], 16;" :: "r"(dst), "l"(src));
}
__device__ __forceinline__ uint32_t bits(__nv_bfloat162 v) {
    return *reinterpret_cast<uint32_t*>(&v);
}

// exact value for non-underflow elements (rare): fp32 dot from global
__device__ __noinline__ float precise_val(const float* __restrict__ X,
                                          const float* __restrict__ Y,
                                          int m, int n, float xpy) {
    const float4* xr = reinterpret_cast<const float4*>(X + (size_t)m * KD);
    const float4* yr = reinterpret_cast<const float4*>(Y + (size_t)n * KD);
    float dot = 0.0f;
#pragma unroll
    for (int i = 0; i < KD / 4; i++) {
        float4 a = xr[i], b = yr[i];
        dot = fmaf(a.x, b.x, dot); dot = fmaf(a.y, b.y, dot);
        dot = fmaf(a.z, b.z, dot); dot = fmaf(a.w, b.w, dot);
    }
    return __expf(-fmaxf(fmaf(-2.0f, dot, xpy), 0.0f));
}

// ---------------- prep: norms + bf16 hi (warp per row) ----------------
__global__ void rbf_prep_kernel(const float* __restrict__ x,
                                const float* __restrict__ y) {
    int gw = (blockIdx.x * blockDim.x + threadIdx.x) >> 5;
    int lane = threadIdx.x & 31;
    if (gw >= 2 * NM) return;
    bool isX = gw < NM;
    int row = isX ? gw : gw - NM;
    const float* src = isX ? x : y;
    __nv_bfloat16* hid = isX ? g_xhi : g_yhi;
    float* nrm = isX ? g_x2 : g_y2;

    float4 v = reinterpret_cast<const float4*>(src + (size_t)row * KD)[lane];
    __nv_bfloat162 h01 = __floats2bfloat162_rn(v.x, v.y);
    __nv_bfloat162 h23 = __floats2bfloat162_rn(v.z, v.w);
    *reinterpret_cast<uint2*>(hid + (size_t)row * KD + lane * 4) =
        make_uint2(bits(h01), bits(h23));

    float s = fmaf(v.x, v.x, fmaf(v.y, v.y, fmaf(v.z, v.z, v.w * v.w)));
#pragma unroll
    for (int o = 16; o > 0; o >>= 1) s += __shfl_xor_sync(0xFFFFFFFFu, s, o);
    if (lane == 0) nrm[row] = s;
}

// ---------------- main MMA filter kernel ----------------
// CTA 128x128, 8 warps (2 M x 4 N), warp tile 64x32, full K=128 resident.
// smem 64 KB (2 CTA/SM): Ahi [0,32K) = 2 k-panels x 16 KB (128 rows x 128B,
// 8 x 16B chunks, chunk ^= row&7); Bhi [32K,64K) same.
// Epilogue: coalesced STG.128 zero-fill of the whole tile, then rare precise
// overwrites guarded by the certified-underflow filter.
__global__ __launch_bounds__(256, 2)
void rbf_mma_kernel(const float* __restrict__ X,
                    const float* __restrict__ Y,
                    float* __restrict__ O) {
    extern __shared__ char sm[];
    __shared__ float x2s[CTA_M];
    __shared__ float y2s[CTA_N];

    const int tid = threadIdx.x;
    const int wid = tid >> 5;
    const int lane = tid & 31;
    const int wm = wid >> 2;       // 0..1 (64 rows)
    const int wn = wid & 3;        // 0..3 (32 cols)
    const int mBase = blockIdx.y * CTA_M;
    const int nBase = blockIdx.x * CTA_N;

    const uint32_t sA = smem_u32(sm);
    const uint32_t sB = sA + 32768u;

#pragma unroll
    for (int i = 0; i < 8; i++) {
        int idx = tid + i * 256;
        int r = idx >> 4, j = idx & 15;
        uint32_t off = (uint32_t)((j >> 3) * 16384 + r * 128 + (((j & 7) ^ (r & 7)) << 4));
        cp16(sA + off, g_xhi + (size_t)(mBase + r) * KD + j * 8);
        cp16(sB + off, g_yhi + (size_t)(nBase + r) * KD + j * 8);
    }
    asm volatile("cp.async.commit_group;" ::: "memory");

    if (tid < CTA_M) x2s[tid] = g_x2[mBase + tid];
    else             y2s[tid - CTA_M] = g_y2[nBase + (tid - CTA_M)];

    float acc[4][4][4];
#pragma unroll
    for (int mt = 0; mt < 4; mt++)
#pragma unroll
        for (int nt = 0; nt < 4; nt++)
#pragma unroll
            for (int r = 0; r < 4; r++) acc[mt][nt][r] = 0.0f;

    const int a_row = wm * 64 + (lane & 15);
    const int a_cs  = lane >> 4;
    const int b_row = wn * 32 + (lane & 7) + ((lane >> 4) << 3);
    const int b_cs  = (lane >> 3) & 1;

    asm volatile("cp.async.wait_group 0;" ::: "memory");
    __syncthreads();

#pragma unroll
    for (int ks = 0; ks < 8; ks++) {
        const uint32_t pnl = (uint32_t)((ks >> 2) * 16384);
        const int kc = (ks & 3) * 2;
        uint32_t bh[2][4];
#pragma unroll
        for (int pr = 0; pr < 2; pr++) {
            int rr = b_row + pr * 16;
            ldsm_x4(bh[pr], sB + pnl + (uint32_t)(rr * 128)
                          + (uint32_t)(((kc + b_cs) ^ (rr & 7)) << 4));
        }
#pragma unroll
        for (int mt = 0; mt < 4; mt++) {
            int rr = a_row + mt * 16;
            uint32_t ah[4];
            ldsm_x4(ah, sA + pnl + (uint32_t)(rr * 128)
                      + (uint32_t)(((kc + a_cs) ^ (rr & 7)) << 4));
#pragma unroll
            for (int pr = 0; pr < 2; pr++) {
                mma_bf16(acc[mt][2 * pr],     ah, bh[pr]);
                mma_bf16(acc[mt][2 * pr + 1], ah, bh[pr] + 2);
            }
        }
    }

    // -------- epilogue part 1: coalesced zero-fill of the 128x128 tile --------
    // 4096 float4s; thread t writes float4 #(t + i*256): row = idx>>5, col4 = idx&31.
    // Each warp instruction covers one full 512B row -> perfect 128B-line coverage.
    {
        const float4 z = make_float4(0.f, 0.f, 0.f, 0.f);
        float4* obase = reinterpret_cast<float4*>(O + (size_t)mBase * NM + nBase);
        const int ldo4 = NM / 4;
#pragma unroll
        for (int i = 0; i < 16; i++) {
            int idx = tid + i * 256;
            int r = idx >> 5, c4 = idx & 31;
            obase[(size_t)r * ldo4 + c4] = z;
        }
    }
    __syncthreads();   // zero-stores visible before sparse overwrites

    // -------- epilogue part 2: rare precise overwrites --------
    const int g  = lane >> 2;
    const int t4 = lane & 3;
#pragma unroll
    for (int mt = 0; mt < 4; mt++) {
        int mrow = wm * 64 + mt * 16 + g;
        float xa = x2s[mrow];
        float xb = x2s[mrow + 8];
        int m0 = mBase + mrow;
#pragma unroll
        for (int nt = 0; nt < 4; nt++) {
            int nc = wn * 32 + nt * 8 + t4 * 2;
            float ya = y2s[nc];
            float yb = y2s[nc + 1];
            const float* a4 = acc[mt][nt];
            int n0 = nBase + nc;
            float c00 = 89.2f + 0.008f * (xa + ya);
            float c01 = 89.2f + 0.008f * (xa + yb);
            float c10 = 89.2f + 0.008f * (xb + ya);
            float c11 = 89.2f + 0.008f * (xb + yb);
            if (fmaf(-2.0f, a4[0], xa + ya) < c00)
                O[(size_t)m0 * NM + n0]           = precise_val(X, Y, m0,     n0,     xa + ya);
            if (fmaf(-2.0f, a4[1], xa + yb) < c01)
                O[(size_t)m0 * NM + n0 + 1]       = precise_val(X, Y, m0,     n0 + 1, xa + yb);
            if (fmaf(-2.0f, a4[2], xb + ya) < c10)
                O[(size_t)(m0 + 8) * NM + n0]     = precise_val(X, Y, m0 + 8, n0,     xb + ya);
            if (fmaf(-2.0f, a4[3], xb + yb) < c11)
                O[(size_t)(m0 + 8) * NM + n0 + 1] = precise_val(X, Y, m0 + 8, n0 + 1, xb + yb);
        }
    }
}

// ---------------------------------------------------------------------------
extern "C" void kernel_launch(void* const* d_in, const int* in_sizes, int n_in,
                              void* d_out, int out_size) {
    const float* x = (const float*)d_in[0];
    const float* y = (const float*)d_in[1];
    float* out = (float*)d_out;

    cudaFuncSetAttribute(rbf_mma_kernel,
                         cudaFuncAttributeMaxDynamicSharedMemorySize, 65536);

    rbf_prep_kernel<<<2048, 256>>>(x, y);

    dim3 grid(NM / CTA_N, NM / CTA_M);   // (64, 64)
    rbf_mma_kernel<<<grid, 256, 65536>>>(x, y, out);
}